// round 6
// baseline (speedup 1.0000x reference)
#include <cuda_runtime.h>
#include <math.h>

#define DIM 1024
#define NTHREADS 256

// Fused integer LayerNorm: one 256-thread block per row (256 x float4 = 1024).
// Per-thread chain: 1 LDG.128 -> partial sums -> warp REDUX -> smem join ->
// apply -> 1 STG.128. Minimal latency chains, maximal resident parallelism.
__global__ __launch_bounds__(NTHREADS)
void iln_fused(const float* __restrict__ x,
               const float* __restrict__ weight,
               const float* __restrict__ bias,
               float* __restrict__ out,
               int n_rows)
{
    __shared__ int s_sum[8];
    __shared__ int s_sq[8];
    __shared__ int4 s_stats;          // {mean, inv, ts, -}

    const int tid  = threadIdx.x;
    const int warp = tid >> 5;
    const int lane = tid & 31;
    const int row  = blockIdx.x;
    if (row >= n_rows) return;

    // One float4 of x per thread (streaming: touched once)
    const float4* __restrict__ xr = (const float4*)(x + (size_t)row * DIM);
    const float4 v = __ldcs(&xr[tid]);

    // Per-thread weight/bias quad (8 KB total, L2/L1-hot across 16384 blocks)
    const float4 w4 = ((const float4*)weight)[tid];
    const float4 b4 = ((const float4*)bias)[tid];

    const int a = __float2int_rn(v.x);
    const int b = __float2int_rn(v.y);
    const int c = __float2int_rn(v.z);
    const int d = __float2int_rn(v.w);

    int sum = a + b + c + d;
    int sq  = a * a + b * b + c * c + d * d;   // block total ~1e8 << 2^31, exact

    sum = __reduce_add_sync(0xffffffffu, sum);
    sq  = __reduce_add_sync(0xffffffffu, sq);
    if (lane == 0) { s_sum[warp] = sum; s_sq[warp] = sq; }
    __syncthreads();

    if (warp == 0) {
        int ts_ = (lane < 8) ? s_sum[lane] : 0;
        int tq_ = (lane < 8) ? s_sq[lane]  : 0;
        ts_ = __reduce_add_sync(0xffffffffu, ts_);
        tq_ = __reduce_add_sync(0xffffffffu, tq_);
        if (lane == 0) {
            const int mean = (ts_ * 64) >> 16;             // fixed-point mean
            const long long ssy = (long long)tq_
                                - 2LL * (long long)mean * (long long)ts_
                                + (long long)DIM * (long long)mean * (long long)mean;
            long long var = (ssy * 64) >> 16;
            if (var < 1) var = 1;
            const int k = 63 - __clzll((unsigned long long)var);  // floor(log2), exact
            const int sa = k - 4;
            const int mant = (sa >= 0) ? (int)((var >> sa) & 15)
                                       : (int)((var << (-sa)) & 15);
            // Single isqrt-LUT entry computed exactly in double:
            // round((1<<15)/sqrt(2^parity * (1 + mant/16)))
            const double val = (double)(1 << (k & 1)) * (1.0 + (double)mant * 0.0625);
            const int inv = (int)llrint(32768.0 / sqrt(val));
            const int ts = (k >> 1) + 15;                  // p + SHIFT(0) + Q_LUT(15)
            s_stats = make_int4(mean, inv, ts, 0);
        }
    }
    __syncthreads();

    const int mean = s_stats.x;
    const int inv  = s_stats.y;
    const int ts   = s_stats.z;

    // Quantize w/b (round-half-even matches jnp.round) and apply
    const int w0 = __float2int_rn(w4.x * 256.0f);
    const int w1 = __float2int_rn(w4.y * 256.0f);
    const int w2 = __float2int_rn(w4.z * 256.0f);
    const int w3 = __float2int_rn(w4.w * 256.0f);
    const int b0 = __float2int_rn(b4.x * 256.0f);
    const int b1 = __float2int_rn(b4.y * 256.0f);
    const int b2 = __float2int_rn(b4.z * 256.0f);
    const int b3 = __float2int_rn(b4.w * 256.0f);

    float4 o;
    long long t;
    t = (((long long)((a - mean) * inv) * (long long)w0) >> ts) + b0;
    o.x = (float)t * 0.00390625f;
    t = (((long long)((b - mean) * inv) * (long long)w1) >> ts) + b1;
    o.y = (float)t * 0.00390625f;
    t = (((long long)((c - mean) * inv) * (long long)w2) >> ts) + b2;
    o.z = (float)t * 0.00390625f;
    t = (((long long)((d - mean) * inv) * (long long)w3) >> ts) + b3;
    o.w = (float)t * 0.00390625f;

    float4* __restrict__ orow = (float4*)(out + (size_t)row * DIM);
    __stcs(&orow[tid], o);
}

extern "C" void kernel_launch(void* const* d_in, const int* in_sizes, int n_in,
                              void* d_out, int out_size) {
    const float* x      = (const float*)d_in[0];
    const float* weight = (const float*)d_in[1];
    const float* bias   = (const float*)d_in[2];
    // d_in[3] (isqrt_lut) intentionally unused: entry recomputed exactly in-kernel.
    float* out = (float*)d_out;

    const int n_rows = in_sizes[0] / DIM;
    iln_fused<<<n_rows, NTHREADS>>>(x, weight, bias, out, n_rows);
}

// round 7
// speedup vs baseline: 1.3589x; 1.3589x over previous
#include <cuda_runtime.h>
#include <math.h>

#define DIM 1024
#define MAX_ROWS 32768
#define ROWS_PER_BLOCK2 4

// Scratch (static __device__ arrays: allocation-free, harness-legal)
__device__ int4 g_stats[MAX_ROWS];   // {mean, inv, ts, 0} per row
__device__ int4 g_wb[DIM / 4];       // packed int16 {w0|w1, w2|w3, b0|b1, b2|b3} per col-quad

// ---------------- K1: per-row statistics (pure read stream, warms L2) ----------------
__global__ __launch_bounds__(256)
void iln_stats(const float* __restrict__ x,
               const float* __restrict__ weight,
               const float* __restrict__ bias,
               int n_rows)
{
    __shared__ int s_lut[32];
    const int tid = threadIdx.x;

    // 32-entry isqrt LUT, exact: round((1<<15)/sqrt(2^parity*(1+m/16)))
    if (tid < 32) {
        const int parity = tid >> 4;
        const int mant = tid & 15;
        const double val = (double)(1 << parity) * (1.0 + (double)mant * 0.0625);
        s_lut[tid] = (int)llrint(32768.0 / sqrt(val));
    }

    // Block 0 packs quantized weight/bias for K2 (round-half-even matches jnp.round)
    if (blockIdx.x == 0) {
        const float4 w4 = ((const float4*)weight)[tid];
        const float4 b4 = ((const float4*)bias)[tid];
        const int w0 = __float2int_rn(w4.x * 256.0f);
        const int w1 = __float2int_rn(w4.y * 256.0f);
        const int w2 = __float2int_rn(w4.z * 256.0f);
        const int w3 = __float2int_rn(w4.w * 256.0f);
        const int b0 = __float2int_rn(b4.x * 256.0f);
        const int b1 = __float2int_rn(b4.y * 256.0f);
        const int b2 = __float2int_rn(b4.z * 256.0f);
        const int b3 = __float2int_rn(b4.w * 256.0f);
        g_wb[tid] = make_int4((w0 & 0xffff) | (w1 << 16),
                              (w2 & 0xffff) | (w3 << 16),
                              (b0 & 0xffff) | (b1 << 16),
                              (b2 & 0xffff) | (b3 << 16));
    }
    __syncthreads();

    const int warp = tid >> 5;
    const int lane = tid & 31;
    const int row = blockIdx.x * 8 + warp;
    if (row >= n_rows) return;

    const float4* __restrict__ xr = (const float4*)(x + (size_t)row * DIM);

    // Front-batched loads: 8 independent LDG.128 (default policy -> L2-resident for K2)
    float4 v[8];
    #pragma unroll
    for (int j = 0; j < 8; j++) v[j] = xr[j * 32 + lane];

    int sum = 0, sumsq = 0;   // row sumsq ~1e8 << 2^31, exact
    #pragma unroll
    for (int j = 0; j < 8; j++) {
        const int a = __float2int_rn(v[j].x);
        const int b = __float2int_rn(v[j].y);
        const int c = __float2int_rn(v[j].z);
        const int d = __float2int_rn(v[j].w);
        sum   += a + b + c + d;
        sumsq += a * a + b * b + c * c + d * d;
    }
    sum   = __reduce_add_sync(0xffffffffu, sum);
    sumsq = __reduce_add_sync(0xffffffffu, sumsq);

    if (lane == 0) {
        const int mean = (sum * 64) >> 16;                 // fixed-point mean
        const long long ssy = (long long)sumsq
                            - 2LL * (long long)mean * (long long)sum
                            + (long long)DIM * (long long)mean * (long long)mean;
        long long var = (ssy * 64) >> 16;
        if (var < 1) var = 1;
        const int k = 63 - __clzll((unsigned long long)var);  // floor(log2), exact
        const int sa = k - 4;
        const int mant = (sa >= 0) ? (int)((var >> sa) & 15)
                                   : (int)((var << (-sa)) & 15);
        const int inv = s_lut[((k & 1) << 4) | mant];
        const int ts = (k >> 1) + 15;                      // p + SHIFT(0) + Q_LUT(15)
        g_stats[row] = make_int4(mean, inv, ts, 0);
    }
}

// ---------------- K2: apply (pure map, 4 rows per block, streaming stores) ----------------
__device__ __forceinline__ float4 apply_quad(float4 v, int mean, int inv, int ts,
                                             int w01, int w23, int b01, int b23)
{
    const int w0 = (w01 << 16) >> 16, w1 = w01 >> 16;
    const int w2 = (w23 << 16) >> 16, w3 = w23 >> 16;
    const int b0 = (b01 << 16) >> 16, b1 = b01 >> 16;
    const int b2 = (b23 << 16) >> 16, b3 = b23 >> 16;
    float4 o;
    long long t;
    t = (((long long)((__float2int_rn(v.x) - mean) * inv) * (long long)w0) >> ts) + b0;
    o.x = (float)t * 0.00390625f;
    t = (((long long)((__float2int_rn(v.y) - mean) * inv) * (long long)w1) >> ts) + b1;
    o.y = (float)t * 0.00390625f;
    t = (((long long)((__float2int_rn(v.z) - mean) * inv) * (long long)w2) >> ts) + b2;
    o.z = (float)t * 0.00390625f;
    t = (((long long)((__float2int_rn(v.w) - mean) * inv) * (long long)w3) >> ts) + b3;
    o.w = (float)t * 0.00390625f;
    return o;
}

__global__ __launch_bounds__(256)
void iln_apply(const float* __restrict__ x,
               float* __restrict__ out,
               int n_rows)
{
    const int tid = threadIdx.x;
    const int row0 = blockIdx.x * ROWS_PER_BLOCK2;

    // Thread tid owns column-quad tid in each of the block's 4 rows.
    const int4 wb = g_wb[tid];

    // Front-batch all x loads (L2-hot from K1) + per-row stats (uniform).
    float4 v[ROWS_PER_BLOCK2];
    int4 st[ROWS_PER_BLOCK2];
    #pragma unroll
    for (int r = 0; r < ROWS_PER_BLOCK2; r++) {
        const int row = row0 + r;
        if (row < n_rows) {
            v[r]  = ((const float4*)(x + (size_t)row * DIM))[tid];
            st[r] = g_stats[row];
        }
    }

    #pragma unroll
    for (int r = 0; r < ROWS_PER_BLOCK2; r++) {
        const int row = row0 + r;
        if (row < n_rows) {
            const float4 o = apply_quad(v[r], st[r].x, st[r].y, st[r].z,
                                        wb.x, wb.y, wb.z, wb.w);
            // Streaming store: don't let the out stream evict L2-resident x.
            __stcs(&((float4*)(out + (size_t)row * DIM))[tid], o);
        }
    }
}

extern "C" void kernel_launch(void* const* d_in, const int* in_sizes, int n_in,
                              void* d_out, int out_size) {
    const float* x      = (const float*)d_in[0];
    const float* weight = (const float*)d_in[1];
    const float* bias   = (const float*)d_in[2];
    // d_in[3] (isqrt_lut) intentionally unused: LUT recomputed exactly in-kernel.
    float* out = (float*)d_out;

    const int n_rows = in_sizes[0] / DIM;

    const int blocks1 = (n_rows + 7) / 8;                       // 8 rows (warps) per block
    iln_stats<<<blocks1, 256>>>(x, weight, bias, n_rows);

    const int blocks2 = (n_rows + ROWS_PER_BLOCK2 - 1) / ROWS_PER_BLOCK2;
    iln_apply<<<blocks2, 256>>>(x, out, n_rows);
}

// round 8
// speedup vs baseline: 1.4881x; 1.0951x over previous
#include <cuda_runtime.h>
#include <math.h>

#define DIM 1024
#define NCONS 5            // consumer warps per block
#define NSLOT 2            // double buffer per consumer
#define NTHREADS 192       // 1 producer warp + 5 consumer warps
#define GRID_BLOCKS 760    // 5 blocks x 152 SMs

// ---- async copy helpers ----
__device__ __forceinline__ void cp_async16(void* smem_dst, const void* gsrc) {
    unsigned saddr = (unsigned)__cvta_generic_to_shared(smem_dst);
    asm volatile("cp.async.cg.shared.global [%0], [%1], 16;\n" :: "r"(saddr), "l"(gsrc));
}
__device__ __forceinline__ void cp_commit() { asm volatile("cp.async.commit_group;\n"); }
template<int N> __device__ __forceinline__ void cp_wait() {
    asm volatile("cp.async.wait_group %0;\n" :: "n"(N));
}

// ---- mbarrier helpers ----
__device__ __forceinline__ unsigned smem_u32(const void* p) {
    return (unsigned)__cvta_generic_to_shared(p);
}
__device__ __forceinline__ void mbar_init(unsigned addr, unsigned count) {
    asm volatile("mbarrier.init.shared.b64 [%0], %1;" :: "r"(addr), "r"(count) : "memory");
}
__device__ __forceinline__ void mbar_arrive(unsigned addr) {
    asm volatile("mbarrier.arrive.shared.b64 _, [%0];" :: "r"(addr) : "memory");
}
__device__ __forceinline__ void mbar_wait(unsigned addr, unsigned parity) {
    unsigned done;
    asm volatile(
        "{\n\t.reg .pred p;\n\t"
        "mbarrier.try_wait.parity.acquire.cta.shared::cta.b64 p, [%1], %2;\n\t"
        "selp.b32 %0, 1, 0, p;\n\t}"
        : "=r"(done) : "r"(addr), "r"(parity) : "memory");
    if (!done) {
        asm volatile(
            "{\n\t.reg .pred P1;\n\t"
            "WL_%=:\n\t"
            "mbarrier.try_wait.parity.acquire.cta.shared::cta.b64 P1, [%0], %1, 0x989680;\n\t"
            "@P1 bra.uni WD_%=;\n\t"
            "bra.uni WL_%=;\n\t"
            "WD_%=:\n\t}"
            :: "r"(addr), "r"(parity) : "memory");
    }
}

__global__ __launch_bounds__(NTHREADS)
void iln_ws(const float* __restrict__ x,
            const float* __restrict__ weight,
            const float* __restrict__ bias,
            float* __restrict__ out,
            int n_rows)
{
    __shared__ float4 s_buf[NCONS][NSLOT][DIM / 4];       // 40 KB row buffers
    __shared__ int4 s_wb[DIM / 4];                         // packed int16 w/b, 4 KB
    __shared__ int s_lut[32];
    __shared__ unsigned long long s_mbar[NCONS][NSLOT][2]; // [0]=full, [1]=empty

    const int tid  = threadIdx.x;
    const int warp = tid >> 5;
    const int lane = tid & 31;

    // ---- init: LUT, packed w/b, mbarriers ----
    if (tid < 32) {
        const int parity = tid >> 4;
        const int mant = tid & 15;
        const double val = (double)(1 << parity) * (1.0 + (double)mant * 0.0625);
        s_lut[tid] = (int)llrint(32768.0 / sqrt(val));     // exact isqrt LUT entry
    }
    for (int i = tid; i < DIM / 4; i += NTHREADS) {
        const float4 w4 = ((const float4*)weight)[i];
        const float4 b4 = ((const float4*)bias)[i];
        const int w0 = __float2int_rn(w4.x * 256.0f);
        const int w1 = __float2int_rn(w4.y * 256.0f);
        const int w2 = __float2int_rn(w4.z * 256.0f);
        const int w3 = __float2int_rn(w4.w * 256.0f);
        const int b0 = __float2int_rn(b4.x * 256.0f);
        const int b1 = __float2int_rn(b4.y * 256.0f);
        const int b2 = __float2int_rn(b4.z * 256.0f);
        const int b3 = __float2int_rn(b4.w * 256.0f);
        s_wb[i] = make_int4((w0 & 0xffff) | (w1 << 16),
                            (w2 & 0xffff) | (w3 << 16),
                            (b0 & 0xffff) | (b1 << 16),
                            (b2 & 0xffff) | (b3 << 16));
    }
    if (tid < NCONS * NSLOT) {
        const int c = tid / NSLOT, j = tid % NSLOT;
        mbar_init(smem_u32(&s_mbar[c][j][0]), 1);          // full: producer lane0
        mbar_init(smem_u32(&s_mbar[c][j][1]), 1);          // empty: consumer lane0
    }
    __syncthreads();

    // Rows of this block: b + i*GRID_BLOCKS, i in [0, R_b)
    const int b = blockIdx.x;
    const int R_b = (b < n_rows) ? ((n_rows - 1 - b) / GRID_BLOCKS + 1) : 0;

    if (warp == 0) {
        // ================= PRODUCER =================
        int next_arrive = 0;
        for (int i = 0; i < R_b; i++) {
            const int c = i % NCONS;
            const int k = i / NCONS;
            const int j = k & 1;
            const unsigned u = (unsigned)(k >> 1);         // per-slot use count
            // backpressure: wait slot empty (first use passes immediately: parity 1)
            mbar_wait(smem_u32(&s_mbar[c][j][1]), (u & 1u) ^ 1u);

            const int row = b + i * GRID_BLOCKS;
            const float4* __restrict__ xr = (const float4*)(x + (size_t)row * DIM);
            #pragma unroll
            for (int q = 0; q < 8; q++)
                cp_async16(&s_buf[c][j][q * 32 + lane], &xr[q * 32 + lane]);
            cp_commit();

            if (i - next_arrive >= 6) {
                cp_wait<6>();                               // group next_arrive complete
                if (lane == 0) {
                    const int ca = next_arrive % NCONS;
                    const int ja = (next_arrive / NCONS) & 1;
                    mbar_arrive(smem_u32(&s_mbar[ca][ja][0]));
                }
                next_arrive++;
            }
        }
        // drain
        cp_wait<0>();
        if (lane == 0) {
            for (; next_arrive < R_b; next_arrive++) {
                const int ca = next_arrive % NCONS;
                const int ja = (next_arrive / NCONS) & 1;
                mbar_arrive(smem_u32(&s_mbar[ca][ja][0]));
            }
        }
    } else {
        // ================= CONSUMERS =================
        const int c = warp - 1;
        const int K_c = (R_b > c) ? ((R_b - 1 - c) / NCONS + 1) : 0;
        for (int k = 0; k < K_c; k++) {
            const int i = c + k * NCONS;
            const int row = b + i * GRID_BLOCKS;
            const int j = k & 1;
            const unsigned u = (unsigned)(k >> 1);
            mbar_wait(smem_u32(&s_mbar[c][j][0]), u & 1u);  // wait data

            // smem -> regs (convert), then release the buffer ASAP
            int xi[32];
            int sum = 0, sumsq = 0;                         // row sumsq ~1e8, exact
            #pragma unroll
            for (int q = 0; q < 8; q++) {
                const float4 v = s_buf[c][j][q * 32 + lane];
                const int a0 = __float2int_rn(v.x);
                const int a1 = __float2int_rn(v.y);
                const int a2 = __float2int_rn(v.z);
                const int a3 = __float2int_rn(v.w);
                xi[q * 4 + 0] = a0; xi[q * 4 + 1] = a1;
                xi[q * 4 + 2] = a2; xi[q * 4 + 3] = a3;
                sum   += a0 + a1 + a2 + a3;
                sumsq += a0 * a0 + a1 * a1 + a2 * a2 + a3 * a3;
            }
            __syncwarp();
            if (lane == 0) mbar_arrive(smem_u32(&s_mbar[c][j][1]));  // slot free

            sum   = __reduce_add_sync(0xffffffffu, sum);
            sumsq = __reduce_add_sync(0xffffffffu, sumsq);

            const int mean = (sum * 64) >> 16;              // fixed-point mean
            const long long ssy = (long long)sumsq
                                - 2LL * (long long)mean * (long long)sum
                                + (long long)DIM * (long long)mean * (long long)mean;
            long long var = (ssy * 64) >> 16;
            if (var < 1) var = 1;
            const int kk = 63 - __clzll((unsigned long long)var);   // floor(log2)
            const int sa = kk - 4;
            const int mant = (sa >= 0) ? (int)((var >> sa) & 15)
                                       : (int)((var << (-sa)) & 15);
            const int inv = s_lut[((kk & 1) << 4) | mant];
            const int ts = (kk >> 1) + 15;                  // p + SHIFT(0) + Q_LUT(15)

            float4* __restrict__ orow = (float4*)(out + (size_t)row * DIM);
            #pragma unroll
            for (int q = 0; q < 8; q++) {
                const int4 wb = s_wb[q * 32 + lane];
                const int w0 = (wb.x << 16) >> 16, w1 = wb.x >> 16;
                const int w2 = (wb.y << 16) >> 16, w3 = wb.y >> 16;
                const int b0 = (wb.z << 16) >> 16, b1 = wb.z >> 16;
                const int b2 = (wb.w << 16) >> 16, b3 = wb.w >> 16;
                float4 o;
                long long t;
                t = (((long long)((xi[q*4+0] - mean) * inv) * (long long)w0) >> ts) + b0;
                o.x = (float)t * 0.00390625f;
                t = (((long long)((xi[q*4+1] - mean) * inv) * (long long)w1) >> ts) + b1;
                o.y = (float)t * 0.00390625f;
                t = (((long long)((xi[q*4+2] - mean) * inv) * (long long)w2) >> ts) + b2;
                o.z = (float)t * 0.00390625f;
                t = (((long long)((xi[q*4+3] - mean) * inv) * (long long)w3) >> ts) + b3;
                o.w = (float)t * 0.00390625f;
                __stcs(&orow[q * 32 + lane], o);
            }
        }
    }
}

extern "C" void kernel_launch(void* const* d_in, const int* in_sizes, int n_in,
                              void* d_out, int out_size) {
    const float* x      = (const float*)d_in[0];
    const float* weight = (const float*)d_in[1];
    const float* bias   = (const float*)d_in[2];
    // d_in[3] (isqrt_lut) intentionally unused: LUT recomputed exactly in-kernel.
    float* out = (float*)d_out;

    const int n_rows = in_sizes[0] / DIM;
    iln_ws<<<GRID_BLOCKS, NTHREADS>>>(x, weight, bias, out, n_rows);
}